// round 1
// baseline (speedup 1.0000x reference)
#include <cuda_runtime.h>
#include <math.h>

// Problem constants
#define Bv   4
#define Lv   1024
#define Dv   1024
#define Hv   16
#define DKv  64
#define Pv   2048          // Lq + Lk
#define MBL  (Bv * Lv)     // 4096

// ---------------- scratch (device globals; no allocation allowed) ----------------
__device__ float g_r  [(size_t)Pv * Dv];          // sinusoidal rel-pos table [P, D]
__device__ float g_hq [(size_t)Hv * MBL * DKv];   // [H][B*L][64]
__device__ float g_hk [(size_t)Hv * MBL * DKv];
__device__ float g_hv [(size_t)Hv * MBL * DKv];
__device__ float g_hr [(size_t)Hv * Pv  * DKv];   // [H][P][64]
__device__ float g_hku[(size_t)Hv * MBL];         // hk . u_w
__device__ float g_hrv[(size_t)Hv * Pv];          // hr . v_w
__device__ float g_s  [(size_t)Bv * Hv * Lv * Lv];// attention scores/probs (256 MB)
__device__ float g_cat[(size_t)MBL * Dv];         // concatenated heads [B*L, H*DV]

// ---------------- relative positional embedding table ----------------
// pos = arange(Lq, -Lk, -1); freq = 1/10000^(2i/DW); interleaved sin/cos, scaled.
__global__ void compute_r_kernel(float* __restrict__ r) {
    int idx = blockIdx.x * blockDim.x + threadIdx.x;
    if (idx >= Pv * Dv) return;
    int p = idx >> 10;         // / 1024
    int d = idx & 1023;
    float pos  = (float)(Lv - p);
    int   half = d >> 1;
    // Match jax: freq = 1.0f / powf(10000, x) with x exact
    float freq = 1.0f / powf(10000.0f, (float)(2 * half) / (float)Dv);
    float ang  = pos * freq;
    float val  = (d & 1) ? cosf(ang) : sinf(ang);
    r[idx] = val * 102.4f;     // INIT * DW = 0.1 * 1024
}

// ---------------- per-head projection GEMM ----------------
// C[h][m][n] = sum_d A[m][d] * W[h][n][d];  A:[M,1024], W:[H,64,1024], C:[H,M,64]
__global__ void proj64_kernel(const float* __restrict__ A,
                              const float* __restrict__ W,
                              float* __restrict__ C, int M) {
    __shared__ float As[32][64];   // [k][m]
    __shared__ float Bs[32][64];   // [k][n]
    const int h  = blockIdx.z;
    const int m0 = blockIdx.x * 64;
    const int tid = threadIdx.x;
    const float* Wh = W + (size_t)h * 64 * 1024;
    const int tr = (tid >> 4) << 2;
    const int tc = (tid & 15) << 2;
    float acc[4][4] = {};
    for (int k0 = 0; k0 < 1024; k0 += 32) {
#pragma unroll
        for (int t = 0; t < 2; t++) {
            int f   = tid + t * 256;
            int row = f >> 3;
            int c4  = (f & 7) << 2;
            float4 va = *(const float4*)(A  + (size_t)(m0 + row) * 1024 + k0 + c4);
            As[c4 + 0][row] = va.x; As[c4 + 1][row] = va.y;
            As[c4 + 2][row] = va.z; As[c4 + 3][row] = va.w;
            float4 vb = *(const float4*)(Wh + (size_t)row * 1024 + k0 + c4);
            Bs[c4 + 0][row] = vb.x; Bs[c4 + 1][row] = vb.y;
            Bs[c4 + 2][row] = vb.z; Bs[c4 + 3][row] = vb.w;
        }
        __syncthreads();
#pragma unroll
        for (int kk = 0; kk < 32; kk++) {
            float4 a4 = *(const float4*)&As[kk][tr];
            float4 b4 = *(const float4*)&Bs[kk][tc];
            float av[4] = {a4.x, a4.y, a4.z, a4.w};
            float bv[4] = {b4.x, b4.y, b4.z, b4.w};
#pragma unroll
            for (int i = 0; i < 4; i++)
#pragma unroll
                for (int j = 0; j < 4; j++)
                    acc[i][j] += av[i] * bv[j];
        }
        __syncthreads();
    }
#pragma unroll
    for (int i = 0; i < 4; i++) {
        float4 o = {acc[i][0], acc[i][1], acc[i][2], acc[i][3]};
        *(float4*)(C + ((size_t)h * M + m0 + tr + i) * 64 + tc) = o;
    }
}

// ---------------- row dot with a 64-vector (bias terms c and d) ----------------
__global__ void rowdot64_kernel(const float* __restrict__ src,
                                const float* __restrict__ vec,
                                float* __restrict__ out, int rows) {
    int gtid = blockIdx.x * blockDim.x + threadIdx.x;
    int warp = gtid >> 5;
    int lane = gtid & 31;
    if (warp >= rows) return;
    const float* s = src + (size_t)warp * 64;
    float v = s[lane] * vec[lane] + s[lane + 32] * vec[lane + 32];
#pragma unroll
    for (int o = 16; o; o >>= 1) v += __shfl_xor_sync(0xffffffffu, v, o);
    if (lane == 0) out[warp] = v;
}

// ---------------- scores: content term + fused relative-shift position term ----------------
// S[b,h,i,j] = ( hq_i.hk_j + hku[j] + hq_i.hr_p + hrv[p] ) / 32,   p = L - i + j
__global__ void score_kernel(const float* __restrict__ hq,
                             const float* __restrict__ hk,
                             const float* __restrict__ hr,
                             const float* __restrict__ hku,
                             const float* __restrict__ hrv,
                             float* __restrict__ S) {
    extern __shared__ float sm[];
    float (*Qs)[64]  = (float(*)[64])sm;            // [k][i]
    float (*Ks)[64]  = (float(*)[64])(sm + 4096);   // [k][j]
    float (*Rs)[128] = (float(*)[128])(sm + 8192);  // [k][band row]
    const int j0 = blockIdx.x * 64;
    const int i0 = blockIdx.y * 64;
    const int bh = blockIdx.z;
    const int b  = bh >> 4;
    const int h  = bh & 15;
    const int tid = threadIdx.x;
    const float* Q = hq + ((size_t)h * MBL + (size_t)b * Lv + i0) * 64;
    const float* K = hk + ((size_t)h * MBL + (size_t)b * Lv + j0) * 64;
    const int pmin = Lv - i0 + j0 - 63;             // band start (>= 1 always)
    const float* R = hr + ((size_t)h * Pv + pmin) * 64;

#pragma unroll
    for (int t = 0; t < 4; t++) {
        int f = tid + t * 256;
        int row = f >> 4;
        int c4  = (f & 15) << 2;
        float4 vq = *(const float4*)(Q + (size_t)row * 64 + c4);
        Qs[c4+0][row]=vq.x; Qs[c4+1][row]=vq.y; Qs[c4+2][row]=vq.z; Qs[c4+3][row]=vq.w;
        float4 vk = *(const float4*)(K + (size_t)row * 64 + c4);
        Ks[c4+0][row]=vk.x; Ks[c4+1][row]=vk.y; Ks[c4+2][row]=vk.z; Ks[c4+3][row]=vk.w;
    }
#pragma unroll
    for (int t = 0; t < 8; t++) {
        int f = tid + t * 256;
        int row = f >> 4;                           // 0..127
        int c4  = (f & 15) << 2;
        int p   = pmin + row;
        float4 vr = make_float4(0.f, 0.f, 0.f, 0.f);
        if (p >= 0 && p < Pv)
            vr = *(const float4*)(R + (size_t)row * 64 + c4);
        Rs[c4+0][row]=vr.x; Rs[c4+1][row]=vr.y; Rs[c4+2][row]=vr.z; Rs[c4+3][row]=vr.w;
    }
    __syncthreads();

    const int tr = (tid >> 4) << 2;
    const int tc = (tid & 15) << 2;
    const int base = 63 - tr + tc - 3;              // rv[t] = Rs[kk][base+t], idx = 3 - di + dj
    float acc[4][4] = {};
#pragma unroll 8
    for (int kk = 0; kk < 64; kk++) {
        float4 a4 = *(const float4*)&Qs[kk][tr];
        float4 b4 = *(const float4*)&Ks[kk][tc];
        float av[4] = {a4.x, a4.y, a4.z, a4.w};
        float bv[4] = {b4.x, b4.y, b4.z, b4.w};
        float rv[7];
#pragma unroll
        for (int t = 0; t < 7; t++) rv[t] = Rs[kk][base + t];
#pragma unroll
        for (int i = 0; i < 4; i++)
#pragma unroll
            for (int j = 0; j < 4; j++)
                acc[i][j] += av[i] * (bv[j] + rv[3 - i + j]);
    }

    const float* hkub = hku + (size_t)h * MBL + (size_t)b * Lv;
    const float* hrvh = hrv + (size_t)h * Pv;
    float* Srow = S + ((size_t)bh * Lv + i0) * Lv + j0;
#pragma unroll
    for (int i = 0; i < 4; i++) {
        int gi = tr + i;
#pragma unroll
        for (int j = 0; j < 4; j++) {
            int gj = tc + j;
            int p  = Lv - (i0 + gi) + (j0 + gj);
            float sc = (acc[i][j] + hkub[j0 + gj] + hrvh[p]) * 0.03125f; // 1/sqrt(1024)
            Srow[(size_t)gi * Lv + gj] = sc;
        }
    }
}

// ---------------- block reductions ----------------
__device__ __forceinline__ float blk_reduce(float v, float* sbuf, bool is_max) {
#pragma unroll
    for (int o = 16; o; o >>= 1) {
        float other = __shfl_xor_sync(0xffffffffu, v, o);
        v = is_max ? fmaxf(v, other) : (v + other);
    }
    int warp = threadIdx.x >> 5, lane = threadIdx.x & 31;
    if (lane == 0) sbuf[warp] = v;
    __syncthreads();
    if (threadIdx.x < 32) {
        float x = (threadIdx.x < 8) ? sbuf[threadIdx.x] : (is_max ? -3.402823466e38f : 0.f);
#pragma unroll
        for (int o = 4; o; o >>= 1) {
            float other = __shfl_xor_sync(0xffffffffu, x, o);
            x = is_max ? fmaxf(x, other) : (x + other);
        }
        if (threadIdx.x == 0) sbuf[0] = x;
    }
    __syncthreads();
    float r = sbuf[0];
    __syncthreads();
    return r;
}

// ---------------- softmax over last dim (row length 1024), in place ----------------
__global__ void softmax_kernel(float* __restrict__ S) {
    __shared__ float sbuf[8];
    float* s = S + (size_t)blockIdx.x * 1024;
    int tid = threadIdx.x;
    float v[4];
#pragma unroll
    for (int t = 0; t < 4; t++) v[t] = s[t * 256 + tid];
    float mx = fmaxf(fmaxf(v[0], v[1]), fmaxf(v[2], v[3]));
    mx = blk_reduce(mx, sbuf, true);
    float sum = 0.f;
#pragma unroll
    for (int t = 0; t < 4; t++) { v[t] = expf(v[t] - mx); sum += v[t]; }
    sum = blk_reduce(sum, sbuf, false);
    float inv = 1.0f / sum;
#pragma unroll
    for (int t = 0; t < 4; t++) s[t * 256 + tid] = v[t] * inv;
}

// ---------------- heads = A @ V, written straight into concat layout ----------------
__global__ void av_kernel(const float* __restrict__ S,
                          const float* __restrict__ hv,
                          float* __restrict__ cat) {
    __shared__ float As[32][64];   // [j][i]
    __shared__ float Vs[32][64];   // [j][k]
    const int i0 = blockIdx.x * 64;
    const int bh = blockIdx.y;
    const int b = bh >> 4, h = bh & 15;
    const int tid = threadIdx.x;
    const float* Sb = S  + ((size_t)bh * Lv + i0) * Lv;
    const float* V  = hv + ((size_t)h * MBL + (size_t)b * Lv) * 64;
    const int tr = (tid >> 4) << 2;
    const int tc = (tid & 15) << 2;
    float acc[4][4] = {};
    for (int j0 = 0; j0 < Lv; j0 += 32) {
#pragma unroll
        for (int t = 0; t < 2; t++) {
            int f   = tid + t * 256;
            int row = f >> 3;                       // i within tile
            int c4  = (f & 7) << 2;                 // j within tile
            float4 va = *(const float4*)(Sb + (size_t)row * Lv + j0 + c4);
            As[c4+0][row]=va.x; As[c4+1][row]=va.y; As[c4+2][row]=va.z; As[c4+3][row]=va.w;
            int jr  = f >> 4;                       // 0..31
            int vc4 = (f & 15) << 2;
            *(float4*)&Vs[jr][vc4] = *(const float4*)(V + (size_t)(j0 + jr) * 64 + vc4);
        }
        __syncthreads();
#pragma unroll
        for (int kk = 0; kk < 32; kk++) {
            float4 a4 = *(const float4*)&As[kk][tr];
            float4 v4 = *(const float4*)&Vs[kk][tc];
            float av[4] = {a4.x, a4.y, a4.z, a4.w};
            float vv[4] = {v4.x, v4.y, v4.z, v4.w};
#pragma unroll
            for (int i = 0; i < 4; i++)
#pragma unroll
                for (int j = 0; j < 4; j++)
                    acc[i][j] += av[i] * vv[j];
        }
        __syncthreads();
    }
#pragma unroll
    for (int i = 0; i < 4; i++) {
        float4 o = {acc[i][0], acc[i][1], acc[i][2], acc[i][3]};
        *(float4*)(cat + ((size_t)b * Lv + i0 + tr + i) * 1024 + h * 64 + tc) = o;
    }
}

// ---------------- output projection + residual ----------------
// X[m][n] = sum_d cat[m][d]*Wp[n][d] + q[m][n]
__global__ void outproj_kernel(const float* __restrict__ cat,
                               const float* __restrict__ Wp,
                               const float* __restrict__ qres,
                               float* __restrict__ X) {
    __shared__ float As[32][64];
    __shared__ float Bs[32][64];
    const int n0 = blockIdx.x * 64;
    const int m0 = blockIdx.y * 64;
    const int tid = threadIdx.x;
    const int tr = (tid >> 4) << 2;
    const int tc = (tid & 15) << 2;
    float acc[4][4] = {};
    for (int k0 = 0; k0 < 1024; k0 += 32) {
#pragma unroll
        for (int t = 0; t < 2; t++) {
            int f   = tid + t * 256;
            int row = f >> 3;
            int c4  = (f & 7) << 2;
            float4 va = *(const float4*)(cat + (size_t)(m0 + row) * 1024 + k0 + c4);
            As[c4+0][row]=va.x; As[c4+1][row]=va.y; As[c4+2][row]=va.z; As[c4+3][row]=va.w;
            float4 vb = *(const float4*)(Wp + (size_t)(n0 + row) * 1024 + k0 + c4);
            Bs[c4+0][row]=vb.x; Bs[c4+1][row]=vb.y; Bs[c4+2][row]=vb.z; Bs[c4+3][row]=vb.w;
        }
        __syncthreads();
#pragma unroll
        for (int kk = 0; kk < 32; kk++) {
            float4 a4 = *(const float4*)&As[kk][tr];
            float4 b4 = *(const float4*)&Bs[kk][tc];
            float av[4] = {a4.x, a4.y, a4.z, a4.w};
            float bv[4] = {b4.x, b4.y, b4.z, b4.w};
#pragma unroll
            for (int i = 0; i < 4; i++)
#pragma unroll
                for (int j = 0; j < 4; j++)
                    acc[i][j] += av[i] * bv[j];
        }
        __syncthreads();
    }
#pragma unroll
    for (int i = 0; i < 4; i++)
#pragma unroll
        for (int j = 0; j < 4; j++) {
            size_t idx = (size_t)(m0 + tr + i) * 1024 + n0 + tc + j;
            X[idx] = acc[i][j] + qres[idx];
        }
}

// ---------------- LayerNorm (unbiased std, eps added to std), in place ----------------
__global__ void ln_kernel(float* __restrict__ X,
                          const float* __restrict__ scale,
                          const float* __restrict__ offset) {
    __shared__ float sbuf[8];
    float* x = X + (size_t)blockIdx.x * 1024;
    int tid = threadIdx.x;
    float v[4];
#pragma unroll
    for (int t = 0; t < 4; t++) v[t] = x[t * 256 + tid];
    float sum = v[0] + v[1] + v[2] + v[3];
    sum = blk_reduce(sum, sbuf, false);
    float mean = sum * (1.0f / 1024.0f);
    float ss = 0.f;
#pragma unroll
    for (int t = 0; t < 4; t++) { float d = v[t] - mean; ss += d * d; }
    ss = blk_reduce(ss, sbuf, false);
    float stdv = sqrtf(ss * (1.0f / 1023.0f));
    float inv  = 1.0f / (stdv + 1e-9f);
#pragma unroll
    for (int t = 0; t < 4; t++) {
        int n = t * 256 + tid;
        x[n] = scale[n] * (v[t] - mean) * inv + offset[n];
    }
}

// ---------------- launch ----------------
extern "C" void kernel_launch(void* const* d_in, const int* in_sizes, int n_in,
                              void* d_out, int out_size) {
    (void)in_sizes; (void)n_in; (void)out_size;
    const float* q        = (const float*)d_in[0];
    const float* k        = (const float*)d_in[1];
    const float* v        = (const float*)d_in[2];
    const float* Wq       = (const float*)d_in[3];
    const float* Wk       = (const float*)d_in[4];
    const float* Wv       = (const float*)d_in[5];
    const float* Wr       = (const float*)d_in[6];
    const float* u_w      = (const float*)d_in[7];
    const float* v_w      = (const float*)d_in[8];
    const float* w_proj   = (const float*)d_in[9];
    const float* ln_scale = (const float*)d_in[10];
    const float* ln_off   = (const float*)d_in[11];
    float* out = (float*)d_out;

    float *p_r, *p_hq, *p_hk, *p_hv, *p_hr, *p_hku, *p_hrv, *p_s, *p_cat;
    cudaGetSymbolAddress((void**)&p_r,   g_r);
    cudaGetSymbolAddress((void**)&p_hq,  g_hq);
    cudaGetSymbolAddress((void**)&p_hk,  g_hk);
    cudaGetSymbolAddress((void**)&p_hv,  g_hv);
    cudaGetSymbolAddress((void**)&p_hr,  g_hr);
    cudaGetSymbolAddress((void**)&p_hku, g_hku);
    cudaGetSymbolAddress((void**)&p_hrv, g_hrv);
    cudaGetSymbolAddress((void**)&p_s,   g_s);
    cudaGetSymbolAddress((void**)&p_cat, g_cat);

    compute_r_kernel<<<(Pv * Dv + 255) / 256, 256>>>(p_r);

    proj64_kernel<<<dim3(MBL / 64, 1, Hv), 256>>>(q,   Wq, p_hq, MBL);
    proj64_kernel<<<dim3(MBL / 64, 1, Hv), 256>>>(k,   Wk, p_hk, MBL);
    proj64_kernel<<<dim3(MBL / 64, 1, Hv), 256>>>(v,   Wv, p_hv, MBL);
    proj64_kernel<<<dim3(Pv  / 64, 1, Hv), 256>>>(p_r, Wr, p_hr, Pv);

    rowdot64_kernel<<<(Hv * MBL) / 8, 256>>>(p_hk, u_w, p_hku, Hv * MBL);
    rowdot64_kernel<<<(Hv * Pv)  / 8, 256>>>(p_hr, v_w, p_hrv, Hv * Pv);

    cudaFuncSetAttribute(score_kernel, cudaFuncAttributeMaxDynamicSharedMemorySize, 65536);
    score_kernel<<<dim3(Lv / 64, Lv / 64, Bv * Hv), 256, 65536>>>(
        p_hq, p_hk, p_hr, p_hku, p_hrv, p_s);

    softmax_kernel<<<Bv * Hv * Lv, 256>>>(p_s);

    av_kernel<<<dim3(Lv / 64, Bv * Hv), 256>>>(p_s, p_hv, p_cat);

    outproj_kernel<<<dim3(1024 / 64, MBL / 64), 256>>>(p_cat, w_proj, q, out);

    ln_kernel<<<MBL, 256>>>(out, ln_scale, ln_off);
}

// round 3
// speedup vs baseline: 1.9497x; 1.9497x over previous
#include <cuda_runtime.h>
#include <cstdint>
#include <math.h>

// Problem constants
#define Bv   4
#define Lv   1024
#define Dv   1024
#define Pv   2048
#define MBL  4096

// ---------------- scratch (device globals) ----------------
__device__ float g_r   [(size_t)Pv  * Dv];    // rel-pos table [P, D]
__device__ float g_hqu [(size_t)MBL * Dv];    // hq + u_w
__device__ float g_hqv [(size_t)MBL * Dv];    // hq + v_w
__device__ float g_hk  [(size_t)MBL * Dv];    // hk
__device__ float g_hv  [(size_t)MBL * Dv];    // hv (normal layout)
__device__ float g_hr  [(size_t)Pv  * Dv];    // hr [P][H*64]
__device__ float g_s   [(size_t)64 * Lv * Lv];   // content scores -> probs
__device__ float g_pos [(size_t)64 * Lv * Pv];   // position scores (banded fill)
__device__ float g_cat [(size_t)MBL * Dv];    // concatenated heads

// ================= helpers =================
__device__ __forceinline__ uint32_t smem_u32(const void* p) {
    uint32_t a;
    asm("{ .reg .u64 t; cvta.to.shared.u64 t, %1; cvt.u32.u64 %0, t; }" : "=r"(a) : "l"(p));
    return a;
}
__device__ __forceinline__ void cpasync16(uint32_t dst, const float* src) {
    asm volatile("cp.async.cg.shared.global [%0], [%1], 16;" :: "r"(dst), "l"(src) : "memory");
}
__device__ __forceinline__ void cp_commit() { asm volatile("cp.async.commit_group;" ::: "memory"); }
template <int N> __device__ __forceinline__ void cp_wait() {
    asm volatile("cp.async.wait_group %0;" :: "n"(N) : "memory");
}
__device__ __forceinline__ uint32_t cvt_tf32(float x) {
    uint32_t r; asm("cvt.rna.tf32.f32 %0, %1;" : "=r"(r) : "f"(x)); return r;
}
__device__ __forceinline__ void mma8(float* c, const uint32_t* a, const uint32_t* b) {
    asm volatile("mma.sync.aligned.m16n8k8.row.col.f32.tf32.tf32.f32 "
        "{%0,%1,%2,%3}, {%4,%5,%6,%7}, {%8,%9}, {%0,%1,%2,%3};"
        : "+f"(c[0]), "+f"(c[1]), "+f"(c[2]), "+f"(c[3])
        : "r"(a[0]), "r"(a[1]), "r"(a[2]), "r"(a[3]), "r"(b[0]), "r"(b[1]));
}

// ================= generic tf32 warp-MMA GEMM =================
// C[z][m][n] = sum_k A[...m,k] * B[...n,k]   (B_KN: B stored [k][n] rows)
// z = zb*16+zh; offsets via *_bs (batch) and *_hs (head) element strides.
// EPI: 0 plain, 1 dual write +uvec/+vvec, 3 residual add.  X3: 3xTF32 split.
template <int N_TILE, int EPI, bool B_KN, bool X3>
__global__ void __launch_bounds__(256) gemm_mma(
    const float* __restrict__ A, int lda, long long a_bs, long long a_hs,
    const float* __restrict__ B, int ldb, long long b_bs, long long b_hs,
    float* __restrict__ C, float* __restrict__ C2, int ldc, long long c_bs, long long c_hs,
    const float* __restrict__ res, const float* __restrict__ uvec, const float* __restrict__ vvec,
    int K, int band)
{
    constexpr int WARPS_M = (N_TILE == 128) ? 2 : 4;
    constexpr int WARPS_N = 8 / WARPS_M;
    constexpr int WM = 128 / WARPS_M;
    constexpr int WN = N_TILE / WARPS_N;
    constexpr int MF = WM / 16;
    constexpr int NF = WN / 8;
    constexpr int AS    = 36;   // A smem row stride (floats): 32 + 4 pad
    constexpr int BS_NK = 36;
    constexpr int BS_KN = 72;   // (8t+g)%32 unique -> conflict-free
    constexpr int A_FL = 128 * AS;
    constexpr int B_FL = B_KN ? 32 * BS_KN : N_TILE * BS_NK;

    extern __shared__ float sh[];
    float* Abuf[2] = { sh, sh + A_FL };
    float* Bbuf[2] = { sh + 2 * A_FL, sh + 2 * A_FL + B_FL };
    const uint32_t shu = smem_u32(sh);
    const uint32_t Au[2] = { shu, shu + (uint32_t)A_FL * 4 };
    const uint32_t Bu[2] = { shu + (uint32_t)(2 * A_FL) * 4, shu + (uint32_t)(2 * A_FL + B_FL) * 4 };

    const int tid = threadIdx.x;
    const int wid = tid >> 5;
    const int lane = tid & 31;
    const int g  = lane >> 2;
    const int t4 = lane & 3;
    const int wm = wid % WARPS_M;
    const int wn = wid / WARPS_M;

    const int z = blockIdx.z, zb = z >> 4, zh = z & 15;
    const int m0 = blockIdx.x * 128;
    const int n0 = blockIdx.y * N_TILE + (band ? (896 - m0) : 0);
    const float* Abase = A + (size_t)zb * a_bs + (size_t)zh * a_hs + (size_t)m0 * lda;
    const float* Bbase = B + (size_t)zb * b_bs + (size_t)zh * b_hs
                           + (B_KN ? (size_t)n0 : (size_t)n0 * ldb);
    const size_t coff = (size_t)zb * c_bs + (size_t)zh * c_hs;

    auto load_chunk = [&](int k0, int buf) {
        uint32_t sA = Au[buf], sB = Bu[buf];
#pragma unroll
        for (int s = tid; s < 1024; s += 256) {
            int r = s >> 3, c = s & 7;
            cpasync16(sA + (uint32_t)(r * (AS * 4) + c * 16), Abase + (size_t)r * lda + k0 + c * 4);
        }
        if (B_KN) {
#pragma unroll
            for (int s = tid; s < 32 * (N_TILE / 4); s += 256) {
                int r = s / (N_TILE / 4), c = s % (N_TILE / 4);
                cpasync16(sB + (uint32_t)(r * (BS_KN * 4) + c * 16), Bbase + (size_t)(k0 + r) * ldb + c * 4);
            }
        } else {
#pragma unroll
            for (int s = tid; s < N_TILE * 8; s += 256) {
                int r = s >> 3, c = s & 7;
                cpasync16(sB + (uint32_t)(r * (BS_NK * 4) + c * 16), Bbase + (size_t)r * ldb + k0 + c * 4);
            }
        }
        cp_commit();
    };

    float acc[MF][NF][4] = {};

    const int NK = K >> 5;
    load_chunk(0, 0);
    if (NK > 1) load_chunk(32, 1);

    for (int kt = 0; kt < NK; kt++) {
        if (kt + 1 < NK) cp_wait<1>(); else cp_wait<0>();
        __syncthreads();
        const float* Asb = Abuf[kt & 1];
        const float* Bsb = Bbuf[kt & 1];
#pragma unroll
        for (int kk = 0; kk < 4; kk++) {
            uint32_t ah[MF][4], al[MF][4];
            uint32_t bh[NF][2], bl[NF][2];
#pragma unroll
            for (int mf = 0; mf < MF; mf++) {
                const float* ap = Asb + (size_t)(wm * WM + mf * 16 + g) * AS + kk * 8 + t4;
                float x0 = ap[0], x1 = ap[8 * AS], x2 = ap[4], x3 = ap[8 * AS + 4];
                ah[mf][0] = cvt_tf32(x0); ah[mf][1] = cvt_tf32(x1);
                ah[mf][2] = cvt_tf32(x2); ah[mf][3] = cvt_tf32(x3);
                if constexpr (X3) {
                    al[mf][0] = cvt_tf32(x0 - __uint_as_float(ah[mf][0]));
                    al[mf][1] = cvt_tf32(x1 - __uint_as_float(ah[mf][1]));
                    al[mf][2] = cvt_tf32(x2 - __uint_as_float(ah[mf][2]));
                    al[mf][3] = cvt_tf32(x3 - __uint_as_float(ah[mf][3]));
                }
            }
#pragma unroll
            for (int nf = 0; nf < NF; nf++) {
                float y0, y1;
                if (B_KN) {
                    const float* bp = Bsb + (size_t)(kk * 8 + t4) * BS_KN + wn * WN + nf * 8 + g;
                    y0 = bp[0]; y1 = bp[4 * BS_KN];
                } else {
                    const float* bp = Bsb + (size_t)(wn * WN + nf * 8 + g) * BS_NK + kk * 8 + t4;
                    y0 = bp[0]; y1 = bp[4];
                }
                bh[nf][0] = cvt_tf32(y0); bh[nf][1] = cvt_tf32(y1);
                if constexpr (X3) {
                    bl[nf][0] = cvt_tf32(y0 - __uint_as_float(bh[nf][0]));
                    bl[nf][1] = cvt_tf32(y1 - __uint_as_float(bh[nf][1]));
                }
            }
#pragma unroll
            for (int mf = 0; mf < MF; mf++)
#pragma unroll
                for (int nf = 0; nf < NF; nf++) {
                    if constexpr (X3) {
                        mma8(acc[mf][nf], al[mf], bh[nf]);
                        mma8(acc[mf][nf], ah[mf], bl[nf]);
                    }
                    mma8(acc[mf][nf], ah[mf], bh[nf]);
                }
        }
        __syncthreads();
        if (kt + 2 < NK) load_chunk((kt + 2) * 32, kt & 1);
    }

    // ---------------- epilogue ----------------
#pragma unroll
    for (int mf = 0; mf < MF; mf++) {
#pragma unroll
        for (int nf = 0; nf < NF; nf++) {
            const float* a = acc[mf][nf];
            const int row = m0 + wm * WM + mf * 16 + g;
            const int col = n0 + wn * WN + nf * 8 + 2 * t4;
            if constexpr (EPI == 0) {
                *(float2*)(C + coff + (size_t)row * ldc + col)       = make_float2(a[0], a[1]);
                *(float2*)(C + coff + (size_t)(row + 8) * ldc + col) = make_float2(a[2], a[3]);
            } else if constexpr (EPI == 1) {
                const int bi = col & 63;
                const float u0 = uvec[bi], u1 = uvec[bi + 1];
                const float v0 = vvec[bi], v1 = vvec[bi + 1];
                const size_t o1 = coff + (size_t)row * ldc + col;
                const size_t o2 = coff + (size_t)(row + 8) * ldc + col;
                *(float2*)(C  + o1) = make_float2(a[0] + u0, a[1] + u1);
                *(float2*)(C  + o2) = make_float2(a[2] + u0, a[3] + u1);
                *(float2*)(C2 + o1) = make_float2(a[0] + v0, a[1] + v1);
                *(float2*)(C2 + o2) = make_float2(a[2] + v0, a[3] + v1);
            } else {
                const size_t o1 = (size_t)row * ldc + col;
                const size_t o2 = (size_t)(row + 8) * ldc + col;
                float2 r1 = *(const float2*)(res + o1);
                float2 r2 = *(const float2*)(res + o2);
                *(float2*)(C + o1) = make_float2(a[0] + r1.x, a[1] + r1.y);
                *(float2*)(C + o2) = make_float2(a[2] + r2.x, a[3] + r2.y);
            }
        }
    }
}

// ---------------- relative positional embedding table ----------------
__global__ void compute_r_kernel(float* __restrict__ r) {
    int idx = blockIdx.x * blockDim.x + threadIdx.x;
    if (idx >= Pv * Dv) return;
    int p = idx >> 10;
    int d = idx & 1023;
    float pos  = (float)(Lv - p);
    int   half = d >> 1;
    float freq = 1.0f / powf(10000.0f, (float)(2 * half) / (float)Dv);
    float ang  = pos * freq;
    float val  = (d & 1) ? cosf(ang) : sinf(ang);
    r[idx] = val * 102.4f;
}

// ---------------- block reduction ----------------
__device__ __forceinline__ float blk_reduce(float v, float* sbuf, bool is_max) {
#pragma unroll
    for (int o = 16; o; o >>= 1) {
        float other = __shfl_xor_sync(0xffffffffu, v, o);
        v = is_max ? fmaxf(v, other) : (v + other);
    }
    int warp = threadIdx.x >> 5, lane = threadIdx.x & 31;
    if (lane == 0) sbuf[warp] = v;
    __syncthreads();
    if (threadIdx.x < 32) {
        float x = (threadIdx.x < 8) ? sbuf[threadIdx.x] : (is_max ? -3.402823466e38f : 0.f);
#pragma unroll
        for (int o = 4; o; o >>= 1) {
            float other = __shfl_xor_sync(0xffffffffu, x, o);
            x = is_max ? fmaxf(x, other) : (x + other);
        }
        if (threadIdx.x == 0) sbuf[0] = x;
    }
    __syncthreads();
    float r = sbuf[0];
    __syncthreads();
    return r;
}

// ---------------- fused relative shift + softmax ----------------
// logits[j] = (Sc[z,i,j] + Sp[z,i, 1024-i+j]) / 32; probs written back into Sc.
__global__ void softmax_fused(const float* __restrict__ Sp, float* __restrict__ S) {
    __shared__ float sbuf[8];
    const int blk = blockIdx.x;
    const int i = blk & 1023;
    float* sc = S + (size_t)blk * 1024;
    const float* sp = Sp + (size_t)blk * 2048 + (1024 - i);
    const int tid = threadIdx.x;
    float v[4];
#pragma unroll
    for (int t = 0; t < 4; t++) {
        int x = t * 256 + tid;
        v[t] = (sc[x] + sp[x]) * 0.03125f;
    }
    float mx = fmaxf(fmaxf(v[0], v[1]), fmaxf(v[2], v[3]));
    mx = blk_reduce(mx, sbuf, true);
    float sum = 0.f;
#pragma unroll
    for (int t = 0; t < 4; t++) { v[t] = expf(v[t] - mx); sum += v[t]; }
    sum = blk_reduce(sum, sbuf, false);
    float inv = 1.0f / sum;
#pragma unroll
    for (int t = 0; t < 4; t++) sc[t * 256 + tid] = v[t] * inv;
}

// ---------------- LayerNorm (unbiased std, eps on std), in place ----------------
__global__ void ln_kernel(float* __restrict__ X,
                          const float* __restrict__ scale,
                          const float* __restrict__ offset) {
    __shared__ float sbuf[8];
    float* x = X + (size_t)blockIdx.x * 1024;
    int tid = threadIdx.x;
    float v[4];
#pragma unroll
    for (int t = 0; t < 4; t++) v[t] = x[t * 256 + tid];
    float sum = v[0] + v[1] + v[2] + v[3];
    sum = blk_reduce(sum, sbuf, false);
    float mean = sum * (1.0f / 1024.0f);
    float ss = 0.f;
#pragma unroll
    for (int t = 0; t < 4; t++) { float d = v[t] - mean; ss += d * d; }
    ss = blk_reduce(ss, sbuf, false);
    float stdv = sqrtf(ss * (1.0f / 1023.0f));
    float inv  = 1.0f / (stdv + 1e-9f);
#pragma unroll
    for (int t = 0; t < 4; t++) {
        int n = t * 256 + tid;
        x[n] = scale[n] * (v[t] - mean) * inv + offset[n];
    }
}

// ---------------- launch ----------------
extern "C" void kernel_launch(void* const* d_in, const int* in_sizes, int n_in,
                              void* d_out, int out_size) {
    (void)in_sizes; (void)n_in; (void)out_size;
    const float* q        = (const float*)d_in[0];
    const float* k        = (const float*)d_in[1];
    const float* v        = (const float*)d_in[2];
    const float* Wq       = (const float*)d_in[3];
    const float* Wk       = (const float*)d_in[4];
    const float* Wv       = (const float*)d_in[5];
    const float* Wr       = (const float*)d_in[6];
    const float* u_w      = (const float*)d_in[7];
    const float* v_w      = (const float*)d_in[8];
    const float* w_proj   = (const float*)d_in[9];
    const float* ln_scale = (const float*)d_in[10];
    const float* ln_off   = (const float*)d_in[11];
    float* out = (float*)d_out;

    float *p_r, *p_hqu, *p_hqv, *p_hk, *p_hv, *p_hr, *p_s, *p_pos, *p_cat;
    cudaGetSymbolAddress((void**)&p_r,   g_r);
    cudaGetSymbolAddress((void**)&p_hqu, g_hqu);
    cudaGetSymbolAddress((void**)&p_hqv, g_hqv);
    cudaGetSymbolAddress((void**)&p_hk,  g_hk);
    cudaGetSymbolAddress((void**)&p_hv,  g_hv);
    cudaGetSymbolAddress((void**)&p_hr,  g_hr);
    cudaGetSymbolAddress((void**)&p_s,   g_s);
    cudaGetSymbolAddress((void**)&p_pos, g_pos);
    cudaGetSymbolAddress((void**)&p_cat, g_cat);

    const int SM128 = (2 * 128 * 36 + 2 * 128 * 36) * 4;  // 73728
    const int SM64K = (2 * 128 * 36 + 2 * 32 * 72) * 4;   // 55296
    cudaFuncSetAttribute(gemm_mma<128,1,false,true>,  cudaFuncAttributeMaxDynamicSharedMemorySize, SM128);
    cudaFuncSetAttribute(gemm_mma<128,0,false,true>,  cudaFuncAttributeMaxDynamicSharedMemorySize, SM128);
    cudaFuncSetAttribute(gemm_mma<128,0,false,false>, cudaFuncAttributeMaxDynamicSharedMemorySize, SM128);
    cudaFuncSetAttribute(gemm_mma<128,3,false,false>, cudaFuncAttributeMaxDynamicSharedMemorySize, SM128);
    cudaFuncSetAttribute(gemm_mma<64,0,true,false>,   cudaFuncAttributeMaxDynamicSharedMemorySize, SM64K);

    compute_r_kernel<<<(Pv * Dv + 255) / 256, 256>>>(p_r);

    // q-proj (3xTF32): hqu = q@Wq^T + u, hqv = q@Wq^T + v
    gemm_mma<128,1,false,true><<<dim3(32, 8, 1), 256, SM128>>>(
        q, 1024, 0, 0, Wq, 1024, 0, 0,
        p_hqu, p_hqv, 1024, 0, 0, nullptr, u_w, v_w, 1024, 0);
    // k-proj (3xTF32)
    gemm_mma<128,0,false,true><<<dim3(32, 8, 1), 256, SM128>>>(
        k, 1024, 0, 0, Wk, 1024, 0, 0,
        p_hk, nullptr, 1024, 0, 0, nullptr, nullptr, nullptr, 1024, 0);
    // v-proj (1x tf32)
    gemm_mma<128,0,false,false><<<dim3(32, 8, 1), 256, SM128>>>(
        v, 1024, 0, 0, Wv, 1024, 0, 0,
        p_hv, nullptr, 1024, 0, 0, nullptr, nullptr, nullptr, 1024, 0);
    // r-proj (3xTF32)
    gemm_mma<128,0,false,true><<<dim3(16, 8, 1), 256, SM128>>>(
        p_r, 1024, 0, 0, Wr, 1024, 0, 0,
        p_hr, nullptr, 1024, 0, 0, nullptr, nullptr, nullptr, 1024, 0);

    // content scores (3xTF32): per bh, [1024,1024] = hqu x hk^T (K=64)
    gemm_mma<128,0,false,true><<<dim3(8, 8, 64), 256, SM128>>>(
        p_hqu, 1024, 1048576LL, 64LL, p_hk, 1024, 1048576LL, 64LL,
        p_s, nullptr, 1024, 16777216LL, 1048576LL, nullptr, nullptr, nullptr, 64, 0);
    // position scores (3xTF32, banded): per bh, 9 p-tiles of [1024,2048]
    gemm_mma<128,0,false,true><<<dim3(8, 9, 64), 256, SM128>>>(
        p_hqv, 1024, 1048576LL, 64LL, p_hr, 1024, 0LL, 64LL,
        p_pos, nullptr, 2048, 33554432LL, 2097152LL, nullptr, nullptr, nullptr, 64, 1);

    // fused relative shift + scale + softmax (probs into g_s)
    softmax_fused<<<64 * Lv, 256>>>(p_pos, p_s);

    // A @ V (1x tf32, B in K-major layout): per bh, [1024,64] (K=1024)
    gemm_mma<64,0,true,false><<<dim3(8, 1, 64), 256, SM64K>>>(
        p_s, 1024, 16777216LL, 1048576LL, p_hv, 1024, 1048576LL, 64LL,
        p_cat, nullptr, 1024, 1048576LL, 64LL, nullptr, nullptr, nullptr, 1024, 0);

    // output projection + residual (1x tf32)
    gemm_mma<128,3,false,false><<<dim3(32, 8, 1), 256, SM128>>>(
        p_cat, 1024, 0, 0, w_proj, 1024, 0, 0,
        out, nullptr, 1024, 0, 0, q, nullptr, nullptr, 1024, 0);

    ln_kernel<<<MBL, 256>>>(out, ln_scale, ln_off);
}